// round 14
// baseline (speedup 1.0000x reference)
#include <cuda_runtime.h>
#include <cuda_fp16.h>
#include <cstdint>

#define BATCH 32
#define TDIM  2048
#define CDIM  384
#define HDIM  64
#define BT    (BATCH * TDIM)
#define NQT2  16                       // 128-row query tiles

// Projected activations in f16. q pre-scaled by 0.125*log2(e) (base-2 softmax).
__device__ __align__(256) __half g_q[BT * HDIM];
__device__ __align__(256) __half g_k[BT * HDIM];
__device__ __align__(256) __half g_v[BT * HDIM];

#define QSCALE 0.1803368801111f   // 0.125 * log2(e)

__device__ __forceinline__ uint32_t packh2(float lo, float hi) {
    uint32_t r;
    asm("cvt.rn.f16x2.f32 %0, %1, %2;" : "=r"(r) : "f"(hi), "f"(lo));
    return r;
}
__device__ __forceinline__ float ex2f(float x) {
    float r; asm("ex2.approx.f32 %0, %1;" : "=f"(r) : "f"(x)); return r;
}
__device__ __forceinline__ uint32_t ex2h2(uint32_t x) {
    uint32_t r; asm("ex2.approx.f16x2 %0, %1;" : "=r"(r) : "r"(x)); return r;
}
__device__ __forceinline__ uint32_t smem_u32(const void* p) {
    uint32_t a;
    asm("{ .reg .u64 t; cvta.to.shared.u64 t, %1; cvt.u32.u64 %0, t; }"
        : "=r"(a) : "l"(p));
    return a;
}
__device__ __forceinline__ void cpa16(uint32_t dst, const void* src) {
    asm volatile("cp.async.cg.shared.global [%0], [%1], 16;"
                 :: "r"(dst), "l"(src));
}
#define CPCOMMIT() asm volatile("cp.async.commit_group;" ::: "memory")
#define CPWAIT(n)  asm volatile("cp.async.wait_group %0;" :: "n"(n) : "memory")

__device__ __forceinline__ void ldm4(uint32_t& r0, uint32_t& r1,
                                     uint32_t& r2, uint32_t& r3, uint32_t a) {
    asm volatile("ldmatrix.sync.aligned.m8n8.x4.shared.b16 {%0,%1,%2,%3}, [%4];"
                 : "=r"(r0), "=r"(r1), "=r"(r2), "=r"(r3) : "r"(a));
}
__device__ __forceinline__ void ldm4t(uint32_t& r0, uint32_t& r1,
                                      uint32_t& r2, uint32_t& r3, uint32_t a) {
    asm volatile("ldmatrix.sync.aligned.m8n8.x4.trans.shared.b16 {%0,%1,%2,%3}, [%4];"
                 : "=r"(r0), "=r"(r1), "=r"(r2), "=r"(r3) : "r"(a));
}

// f16 m16n8k16, fp32 accum.
__device__ __forceinline__ void mma16(float4& c, const uint32_t a[4],
                                      uint32_t b0, uint32_t b1) {
    asm volatile(
        "mma.sync.aligned.m16n8k16.row.col.f32.f16.f16.f32 "
        "{%0,%1,%2,%3}, {%4,%5,%6,%7}, {%8,%9}, {%0,%1,%2,%3};"
        : "+f"(c.x), "+f"(c.y), "+f"(c.z), "+f"(c.w)
        : "r"(a[0]), "r"(a[1]), "r"(a[2]), "r"(a[3]), "r"(b0), "r"(b1));
}

// ---------------------------------------------------------------------------
// Projection, one weight matrix per block: grid (3, BT/128), x-major so the
// 3 mats of a row-block co-run and share x through L2. Block = 256 thr
// (8 warps), 128 rows x 64 cols, 12 k-chunks of 32, double-buffered smem.
// c[8] accumulators -> 2 CTAs/SM.
// ---------------------------------------------------------------------------
#define XPW  20    // Xs pitch in words (32 f16 + pad)
#define WPW2 36    // Ws pitch in words (64 f16 + pad)

__global__ __launch_bounds__(256, 2) void proj_kernel(
    const float* __restrict__ x,
    const float* __restrict__ Wk,
    const float* __restrict__ Wq,
    const float* __restrict__ Wv)
{
    __shared__ uint32_t Xs[2][128 * XPW];
    __shared__ uint32_t Ws[2][32 * WPW2];

    const int t    = threadIdx.x;
    const int warp = t >> 5;
    const int lane = t & 31;
    const int q    = lane & 3;
    const int r4   = lane >> 2;
    const int mat  = blockIdx.x;
    const int row0 = blockIdx.y * 128;
    const float* W = (mat == 0) ? Wk : (mat == 1) ? Wq : Wv;

    const uint32_t ainv = (uint32_t)((warp * 16 + 8 * ((lane >> 3) & 1) + (lane & 7))
                                     * (XPW * 4) + ((lane >> 4) & 1) * 16);
    const uint32_t winv = (uint32_t)((8 * ((lane >> 3) & 1) + (lane & 7)) * (WPW2 * 4)
                                     + 8 * ((lane >> 4) & 1) * 2);

    float4 c[8];
    #pragma unroll
    for (int i = 0; i < 8; i++) c[i] = make_float4(0.f, 0.f, 0.f, 0.f);

    const int xrow = t >> 1, xhalf = t & 1;    // x: 16 f32 per thread
    const int wrow = t >> 3, wc8 = t & 7;      // W: 8 f32 per thread

    float4 xr[2][4], wr[2][2];
    auto loadc = [&](float4 xd[4], float4 wd[2], int cc) {
        const int c0 = cc * 32;
        #pragma unroll
        for (int i = 0; i < 4; i++)
            xd[i] = *(const float4*)&x[(row0 + xrow) * CDIM + c0
                                       + xhalf * 16 + i * 4];
        const float* wp = &W[(c0 + wrow) * HDIM + wc8 * 8];
        wd[0] = *(const float4*)wp;
        wd[1] = *(const float4*)(wp + 4);
    };

    loadc(xr[0], wr[0], 0);
    loadc(xr[1], wr[1], 1);

    #pragma unroll
    for (int cc = 0; cc < 12; cc++) {
        const int ph = cc & 1;
        {
            float4* xv = xr[ph];
            uint4 xp;
            xp.x = packh2(xv[0].x, xv[0].y); xp.y = packh2(xv[0].z, xv[0].w);
            xp.z = packh2(xv[1].x, xv[1].y); xp.w = packh2(xv[1].z, xv[1].w);
            *(uint4*)&Xs[ph][xrow * XPW + xhalf * 8] = xp;
            xp.x = packh2(xv[2].x, xv[2].y); xp.y = packh2(xv[2].z, xv[2].w);
            xp.z = packh2(xv[3].x, xv[3].y); xp.w = packh2(xv[3].z, xv[3].w);
            *(uint4*)&Xs[ph][xrow * XPW + xhalf * 8 + 4] = xp;

            float4* wv = wr[ph];
            uint4 wp;
            wp.x = packh2(wv[0].x, wv[0].y); wp.y = packh2(wv[0].z, wv[0].w);
            wp.z = packh2(wv[1].x, wv[1].y); wp.w = packh2(wv[1].z, wv[1].w);
            *(uint4*)&Ws[ph][wrow * WPW2 + wc8 * 4] = wp;
        }
        __syncthreads();

        if (cc + 2 < 12) loadc(xr[ph], wr[ph], cc + 2);

        const uint32_t xsb = smem_u32(Xs[ph]), wsb = smem_u32(Ws[ph]);
        uint32_t a[2][4];
        ldm4(a[0][0], a[0][1], a[0][2], a[0][3], xsb + ainv);
        ldm4(a[1][0], a[1][1], a[1][2], a[1][3], xsb + ainv + 32);
        #pragma unroll
        for (int nt = 0; nt < 4; nt++)
            #pragma unroll
            for (int kc = 0; kc < 2; kc++) {
                uint32_t b0, b1, b2, b3;
                ldm4t(b0, b1, b2, b3,
                      wsb + winv + (uint32_t)(kc * 16 * WPW2 * 4 + nt * 32));
                mma16(c[2 * nt],     a[kc], b0, b1);
                mma16(c[2 * nt + 1], a[kc], b2, b3);
            }
    }

    const int row = row0 + warp * 16 + r4;
    __half* outp = (mat == 0) ? g_k : (mat == 1) ? g_q : g_v;
    const float sc = (mat == 1) ? QSCALE : 1.0f;
    #pragma unroll
    for (int idx = 0; idx < 8; idx++) {
        const int col = idx * 8 + 2 * q;
        float4 v = c[idx];
        *(uint32_t*)&outp[row * HDIM + col]       = packh2(v.x * sc, v.y * sc);
        *(uint32_t*)&outp[(row + 8) * HDIM + col] = packh2(v.z * sc, v.w * sc);
    }
}

// ---------------------------------------------------------------------------
// Flash attention: 128 q-rows per 128-thr CTA; each warp owns TWO 16-row
// groups (rows wrow..+15, wrow+16..+31). K/V b-frags loaded once feed both
// groups (2x MMA per ldmatrix, 2x ILP in softmax). 128-key staged tiles,
// double-buffered; warp-level diagonal skip.
// ---------------------------------------------------------------------------
#define PW     36
#define T128W  (128 * PW)
#define BUFB   (2 * T128W * 4)
#define ASMEM  (2 * BUFB)

__global__ __launch_bounds__(128, 2) void attn_kernel(float* __restrict__ out)
{
    extern __shared__ uint32_t sm[];
    const uint32_t sb = smem_u32(sm);

    const int t    = threadIdx.x;
    const int b    = blockIdx.y;
    const int warp = t >> 5;
    const int lane = t & 31;
    const int q    = lane & 3;
    const int r4   = lane >> 2;

    const int qt   = (NQT2 - 1) - (int)blockIdx.x;   // heavy first
    const int nkt  = qt + 1;                          // 128-key tiles
    const int wrow = qt * 128 + warp * 32;
    const int rl[2] = { wrow + r4, wrow + 16 + r4 };  // per-group low rows

    const uint32_t kinv = (uint32_t)((8 * ((lane >> 4) & 1) + (lane & 7)) * PW * 4
                                     + 8 * ((lane >> 3) & 1) * 2);
    const uint32_t vinv = (uint32_t)((8 * ((lane >> 3) & 1) + (lane & 7)) * PW * 4
                                     + 8 * ((lane >> 4) & 1) * 2);
    const uint32_t bsum = (r4 == 0) ? 0x3C003C00u : 0u;  // ones col-0 B-frag

    const __half* kb0 = g_k + (size_t)(b * TDIM) * HDIM;
    const __half* vb0 = g_v + (size_t)(b * TDIM) * HDIM;

    auto stage = [&](int kt, int buf) {
        const __half* kb = kb0 + (size_t)kt * 128 * HDIM;
        const __half* vb = vb0 + (size_t)kt * 128 * HDIM;
        const uint32_t kd = sb + (uint32_t)buf * BUFB;
        const uint32_t vd = kd + (uint32_t)T128W * 4;
        #pragma unroll
        for (int i = 0; i < 8; i++) {
            int f = t + i * 128, r = f >> 3, ch = f & 7;
            cpa16(kd + (uint32_t)(r * PW + ch * 4) * 4u, kb + r * HDIM + ch * 8);
            cpa16(vd + (uint32_t)(r * PW + ch * 4) * 4u, vb + r * HDIM + ch * 8);
        }
        CPCOMMIT();
    };

    stage(0, 0);

    uint32_t qa[2][4][4];
    #pragma unroll
    for (int g = 0; g < 2; g++) {
        const __half* qp = g_q + (size_t)(b * TDIM + rl[g]) * HDIM;
        #pragma unroll
        for (int kc = 0; kc < 4; kc++) {
            qa[g][kc][0] = *(const uint32_t*)&qp[16 * kc + 2 * q];
            qa[g][kc][1] = *(const uint32_t*)&qp[8 * HDIM + 16 * kc + 2 * q];
            qa[g][kc][2] = *(const uint32_t*)&qp[16 * kc + 2 * q + 8];
            qa[g][kc][3] = *(const uint32_t*)&qp[8 * HDIM + 16 * kc + 2 * q + 8];
        }
    }

    float4 o[2][8];
    #pragma unroll
    for (int g = 0; g < 2; g++)
        #pragma unroll
        for (int i = 0; i < 8; i++) o[g][i] = make_float4(0.f, 0.f, 0.f, 0.f);
    float m[2][2] = {{-1e30f, -1e30f}, {-1e30f, -1e30f}};
    float l[2][2] = {{0.f, 0.f}, {0.f, 0.f}};

    for (int kt = 0; kt < nkt; kt++) {
        if (kt + 1 < nkt) { stage(kt + 1, (kt + 1) & 1); CPWAIT(1); }
        else              { CPWAIT(0); }
        __syncthreads();

        const uint32_t kbase = sb + (uint32_t)(kt & 1) * BUFB;
        const bool diagtile = (kt == nkt - 1);

        #pragma unroll 1
        for (int sub = 0; sub < 2; sub++) {
            const int cb = kt * 128 + sub * 64;
            if (cb > wrow + 31) break;          // fully masked for this warp

            const uint32_t kb = kbase + kinv + (uint32_t)(sub * 64 * PW * 4);
            const uint32_t vb = kbase + (uint32_t)T128W * 4 + vinv
                                + (uint32_t)(sub * 64 * PW * 4);

            // S = Q @ K^T for both row groups (shared b-frags)
            float4 st[2][8];
            #pragma unroll
            for (int g = 0; g < 2; g++)
                #pragma unroll
                for (int i = 0; i < 8; i++)
                    st[g][i] = make_float4(0.f, 0.f, 0.f, 0.f);
            #pragma unroll
            for (int kc = 0; kc < 4; kc++)
                #pragma unroll
                for (int ncp = 0; ncp < 4; ncp++) {
                    uint32_t b0, b1, b2, b3;
                    ldm4(b0, b1, b2, b3,
                         kb + (uint32_t)(ncp * 16 * PW * 4 + kc * 32));
                    mma16(st[0][2 * ncp],     qa[0][kc], b0, b1);
                    mma16(st[0][2 * ncp + 1], qa[0][kc], b2, b3);
                    mma16(st[1][2 * ncp],     qa[1][kc], b0, b1);
                    mma16(st[1][2 * ncp + 1], qa[1][kc], b2, b3);
                }

            if (diagtile) {
                const int cq = cb + 2 * q;
                #pragma unroll
                for (int g = 0; g < 2; g++)
                    #pragma unroll
                    for (int nc = 0; nc < 8; nc++) {
                        const int col = cq + 8 * nc;
                        if (col > rl[g])         st[g][nc].x = -1e30f;
                        if (col + 1 > rl[g])     st[g][nc].y = -1e30f;
                        if (col > rl[g] + 8)     st[g][nc].z = -1e30f;
                        if (col + 1 > rl[g] + 8) st[g][nc].w = -1e30f;
                    }
            }

            // online softmax (base 2), both groups interleaved
            float corr[2][2];
            #pragma unroll
            for (int g = 0; g < 2; g++) {
                float mx0 = st[g][0].x, mx1 = st[g][0].z;
                #pragma unroll
                for (int nc = 0; nc < 8; nc++) {
                    mx0 = fmaxf(mx0, fmaxf(st[g][nc].x, st[g][nc].y));
                    mx1 = fmaxf(mx1, fmaxf(st[g][nc].z, st[g][nc].w));
                }
                mx0 = fmaxf(mx0, __shfl_xor_sync(0xffffffffu, mx0, 1));
                mx0 = fmaxf(mx0, __shfl_xor_sync(0xffffffffu, mx0, 2));
                mx1 = fmaxf(mx1, __shfl_xor_sync(0xffffffffu, mx1, 1));
                mx1 = fmaxf(mx1, __shfl_xor_sync(0xffffffffu, mx1, 2));
                const float mn0 = fmaxf(m[g][0], mx0), mn1 = fmaxf(m[g][1], mx1);
                corr[g][0] = ex2f(m[g][0] - mn0);
                corr[g][1] = ex2f(m[g][1] - mn1);
                m[g][0] = mn0; m[g][1] = mn1;
                if (__ballot_sync(0xffffffffu,
                                  (corr[g][0] != 1.f) || (corr[g][1] != 1.f))) {
                    #pragma unroll
                    for (int nc = 0; nc < 8; nc++) {
                        o[g][nc].x *= corr[g][0]; o[g][nc].y *= corr[g][0];
                        o[g][nc].z *= corr[g][1]; o[g][nc].w *= corr[g][1];
                    }
                }
            }

            // p = 2^(s-m) as f16x2 A-frags; row sums via HMMA; PV fused.
            float4 sums[2];
            sums[0] = make_float4(0.f, 0.f, 0.f, 0.f);
            sums[1] = make_float4(0.f, 0.f, 0.f, 0.f);
            #pragma unroll
            for (int kc = 0; kc < 4; kc++) {
                uint32_t pa[2][4];
                #pragma unroll
                for (int g = 0; g < 2; g++) {
                    pa[g][0] = ex2h2(packh2(st[g][2*kc].x   - m[g][0],
                                            st[g][2*kc].y   - m[g][0]));
                    pa[g][1] = ex2h2(packh2(st[g][2*kc].z   - m[g][1],
                                            st[g][2*kc].w   - m[g][1]));
                    pa[g][2] = ex2h2(packh2(st[g][2*kc+1].x - m[g][0],
                                            st[g][2*kc+1].y - m[g][0]));
                    pa[g][3] = ex2h2(packh2(st[g][2*kc+1].z - m[g][1],
                                            st[g][2*kc+1].w - m[g][1]));
                    mma16(sums[g], pa[g], bsum, bsum);
                }
                #pragma unroll
                for (int ncp = 0; ncp < 4; ncp++) {
                    uint32_t b0, b1, b2, b3;
                    ldm4t(b0, b1, b2, b3,
                          vb + (uint32_t)(kc * 16 * PW * 4 + ncp * 32));
                    mma16(o[0][2 * ncp],     pa[0], b0, b1);
                    mma16(o[0][2 * ncp + 1], pa[0], b2, b3);
                    mma16(o[1][2 * ncp],     pa[1], b0, b1);
                    mma16(o[1][2 * ncp + 1], pa[1], b2, b3);
                }
            }
            #pragma unroll
            for (int g = 0; g < 2; g++) {
                const float s0 = __shfl_sync(0xffffffffu, sums[g].x, lane & ~3);
                const float s1 = __shfl_sync(0xffffffffu, sums[g].z, lane & ~3);
                l[g][0] = l[g][0] * corr[g][0] + s0;
                l[g][1] = l[g][1] * corr[g][1] + s1;
            }
        }
        __syncthreads();
    }

    // epilogue
    #pragma unroll
    for (int g = 0; g < 2; g++) {
        const float inv0 = 1.0f / l[g][0], inv1 = 1.0f / l[g][1];
        float* ob = out + (size_t)(b * TDIM + rl[g]) * HDIM;
        #pragma unroll
        for (int nc = 0; nc < 8; nc++) {
            const int col = 8 * nc + 2 * q;
            *(float2*)&ob[col] =
                make_float2(o[g][nc].x * inv0, o[g][nc].y * inv0);
            *(float2*)&ob[8 * HDIM + col] =
                make_float2(o[g][nc].z * inv1, o[g][nc].w * inv1);
        }
    }
}

// ---------------------------------------------------------------------------
extern "C" void kernel_launch(void* const* d_in, const int* in_sizes, int n_in,
                              void* d_out, int out_size)
{
    const float* x  = (const float*)d_in[0];
    const float* Wk = (const float*)d_in[1];
    const float* Wq = (const float*)d_in[2];
    const float* Wv = (const float*)d_in[3];
    float* out = (float*)d_out;

    dim3 pgrid(3, BT / 128);           // x-major: 3 mats share x via L2
    proj_kernel<<<pgrid, 256>>>(x, Wk, Wq, Wv);

    cudaFuncSetAttribute(attn_kernel,
                         cudaFuncAttributeMaxDynamicSharedMemorySize, ASMEM);
    dim3 agrid(NQT2, BATCH);
    attn_kernel<<<agrid, 128, ASMEM>>>(out);
}

// round 15
// speedup vs baseline: 1.1539x; 1.1539x over previous
#include <cuda_runtime.h>
#include <cuda_fp16.h>
#include <cstdint>

#define BATCH 32
#define TDIM  2048
#define CDIM  384
#define HDIM  64
#define BT    (BATCH * TDIM)
#define NQT   32

// Projected activations in f16. q pre-scaled by 0.125*log2(e) (base-2 softmax).
__device__ __align__(256) __half g_q[BT * HDIM];
__device__ __align__(256) __half g_k[BT * HDIM];
__device__ __align__(256) __half g_v[BT * HDIM];

#define QSCALE 0.1803368801111f   // 0.125 * log2(e)

__device__ __forceinline__ uint32_t packh2(float lo, float hi) {
    uint32_t r;
    asm("cvt.rn.f16x2.f32 %0, %1, %2;" : "=r"(r) : "f"(hi), "f"(lo));
    return r;
}
__device__ __forceinline__ float ex2f(float x) {
    float r; asm("ex2.approx.f32 %0, %1;" : "=f"(r) : "f"(x)); return r;
}
__device__ __forceinline__ uint32_t ex2h2(uint32_t x) {
    uint32_t r; asm("ex2.approx.f16x2 %0, %1;" : "=r"(r) : "r"(x)); return r;
}
__device__ __forceinline__ uint32_t smem_u32(const void* p) {
    uint32_t a;
    asm("{ .reg .u64 t; cvta.to.shared.u64 t, %1; cvt.u32.u64 %0, t; }"
        : "=r"(a) : "l"(p));
    return a;
}
__device__ __forceinline__ void cpa16(uint32_t dst, const void* src) {
    asm volatile("cp.async.cg.shared.global [%0], [%1], 16;"
                 :: "r"(dst), "l"(src));
}
#define CPCOMMIT() asm volatile("cp.async.commit_group;" ::: "memory")
#define CPWAIT(n)  asm volatile("cp.async.wait_group %0;" :: "n"(n) : "memory")

__device__ __forceinline__ void ldm4(uint32_t& r0, uint32_t& r1,
                                     uint32_t& r2, uint32_t& r3, uint32_t a) {
    asm volatile("ldmatrix.sync.aligned.m8n8.x4.shared.b16 {%0,%1,%2,%3}, [%4];"
                 : "=r"(r0), "=r"(r1), "=r"(r2), "=r"(r3) : "r"(a));
}
__device__ __forceinline__ void ldm4t(uint32_t& r0, uint32_t& r1,
                                      uint32_t& r2, uint32_t& r3, uint32_t a) {
    asm volatile("ldmatrix.sync.aligned.m8n8.x4.trans.shared.b16 {%0,%1,%2,%3}, [%4];"
                 : "=r"(r0), "=r"(r1), "=r"(r2), "=r"(r3) : "r"(a));
}

// f16 m16n8k16, fp32 accum.
__device__ __forceinline__ void mma16(float4& c, const uint32_t a[4],
                                      uint32_t b0, uint32_t b1) {
    asm volatile(
        "mma.sync.aligned.m16n8k16.row.col.f32.f16.f16.f32 "
        "{%0,%1,%2,%3}, {%4,%5,%6,%7}, {%8,%9}, {%0,%1,%2,%3};"
        : "+f"(c.x), "+f"(c.y), "+f"(c.z), "+f"(c.w)
        : "r"(a[0]), "r"(a[1]), "r"(a[2]), "r"(a[3]), "r"(b0), "r"(b1));
}

// ---------------------------------------------------------------------------
// Projection: [K|Q|V] = x @ [Wk|Wq|Wv], f16 m16n8k16 + ldmatrix.
// Block = 512 thr (16 warps = 4/SMSP), 128 rows x 192 cols, ONE x read.
// Warp grid: 8 row-groups x 2 col-groups; each warp 16 rows x 96 cols
// (c[12] = 48 accum regs). 12 k-chunks of 32, register-prefetched staging.
// ---------------------------------------------------------------------------
#define XPW 20     // Xs pitch in words (32 f16 + pad)
#define WPW 100    // Ws pitch in words (192 f16 + pad)

__global__ __launch_bounds__(512, 1) void proj_kernel(
    const float* __restrict__ x,
    const float* __restrict__ Wk,
    const float* __restrict__ Wq,
    const float* __restrict__ Wv)
{
    __shared__ uint32_t Xs[128 * XPW];
    __shared__ uint32_t Ws[32 * WPW];

    const int t    = threadIdx.x;
    const int wid  = t >> 5;
    const int lane = t & 31;
    const int q    = lane & 3;
    const int r4   = lane >> 2;
    const int rowg = wid & 7;      // 8 row-groups of 16 rows
    const int colg = wid >> 3;     // 2 col-groups of 96 cols
    const int row0 = blockIdx.x * 128;
    const float* Wm[3] = {Wk, Wq, Wv};

    const uint32_t ainv = (uint32_t)((rowg * 16 + 8 * ((lane >> 3) & 1) + (lane & 7))
                                     * (XPW * 4) + ((lane >> 4) & 1) * 16);
    const uint32_t winv = (uint32_t)((8 * ((lane >> 3) & 1) + (lane & 7)) * (WPW * 4)
                                     + 8 * ((lane >> 4) & 1) * 2 + colg * 192);
    const uint32_t xsb = smem_u32(Xs), wsb = smem_u32(Ws);

    float4 c[12];
    #pragma unroll
    for (int i = 0; i < 12; i++) c[i] = make_float4(0.f, 0.f, 0.f, 0.f);

    // staging maps: x — thread t -> row t>>2, col-8-group t&3 (16 f32)
    //               W — unit u: row u/24, c8 u%24 (8 f32); u = t and t+512 (t<256)
    const int xrow = t >> 2, xc8 = t & 3;
    const int w0row = t / 24,         w0c8 = t % 24;
    const int w1row = (t + 512) / 24, w1c8 = (t + 512) % 24;

    float4 xr[2], wr0[2], wr1[2];
    auto loadc = [&](int cc) {
        const int c0 = cc * 32;
        const float* xp = &x[(row0 + xrow) * CDIM + c0 + xc8 * 8];
        xr[0] = *(const float4*)xp;
        xr[1] = *(const float4*)(xp + 4);
        const float* wp0 = &Wm[w0c8 >> 3][(c0 + w0row) * HDIM + (w0c8 & 7) * 8];
        wr0[0] = *(const float4*)wp0;
        wr0[1] = *(const float4*)(wp0 + 4);
        if (t < 256) {
            const float* wp1 = &Wm[w1c8 >> 3][(c0 + w1row) * HDIM + (w1c8 & 7) * 8];
            wr1[0] = *(const float4*)wp1;
            wr1[1] = *(const float4*)(wp1 + 4);
        }
    };

    loadc(0);

    for (int cc = 0; cc < 12; cc++) {
        __syncthreads();     // previous chunk's MMA reads complete
        {
            uint4 p;
            p.x = packh2(xr[0].x, xr[0].y); p.y = packh2(xr[0].z, xr[0].w);
            p.z = packh2(xr[1].x, xr[1].y); p.w = packh2(xr[1].z, xr[1].w);
            *(uint4*)&Xs[xrow * XPW + xc8 * 4] = p;

            p.x = packh2(wr0[0].x, wr0[0].y); p.y = packh2(wr0[0].z, wr0[0].w);
            p.z = packh2(wr0[1].x, wr0[1].y); p.w = packh2(wr0[1].z, wr0[1].w);
            *(uint4*)&Ws[w0row * WPW + w0c8 * 4] = p;
            if (t < 256) {
                p.x = packh2(wr1[0].x, wr1[0].y); p.y = packh2(wr1[0].z, wr1[0].w);
                p.z = packh2(wr1[1].x, wr1[1].y); p.w = packh2(wr1[1].z, wr1[1].w);
                *(uint4*)&Ws[w1row * WPW + w1c8 * 4] = p;
            }
        }
        __syncthreads();

        if (cc + 1 < 12) loadc(cc + 1);

        uint32_t a[2][4];
        ldm4(a[0][0], a[0][1], a[0][2], a[0][3], xsb + ainv);
        ldm4(a[1][0], a[1][1], a[1][2], a[1][3], xsb + ainv + 32);
        #pragma unroll
        for (int p5 = 0; p5 < 6; p5++)
            #pragma unroll
            for (int kc = 0; kc < 2; kc++) {
                uint32_t b0, b1, b2, b3;
                ldm4t(b0, b1, b2, b3,
                      wsb + winv + (uint32_t)(kc * 16 * WPW * 4 + p5 * 32));
                mma16(c[2 * p5],     a[kc], b0, b1);
                mma16(c[2 * p5 + 1], a[kc], b2, b3);
            }
    }

    const int row = row0 + rowg * 16 + r4;
    __half* outp[3] = {g_k, g_q, g_v};
    #pragma unroll
    for (int idx = 0; idx < 12; idx++) {
        const int gcol = colg * 96 + idx * 8 + 2 * q;
        const int mat  = gcol >> 6, col = gcol & 63;
        const float sc = (mat == 1) ? QSCALE : 1.0f;   // Q pre-scaled (base-2)
        float4 v = c[idx];
        *(uint32_t*)&outp[mat][row * HDIM + col]       = packh2(v.x * sc, v.y * sc);
        *(uint32_t*)&outp[mat][(row + 8) * HDIM + col] = packh2(v.z * sc, v.w * sc);
    }
}

// ---------------------------------------------------------------------------
// Flash attention (exact R11 version, 82.4 us measured): f16 m16n8k16 +
// ldmatrix, base-2 softmax with f16x2 EX2 and tensor-core row sums.
// Block = 128 thr, 64 q-rows, 128-key staging, double-buffered.
// ---------------------------------------------------------------------------
#define PW     36
#define T128W  (128 * PW)
#define BUFB   (2 * T128W * 4)
#define ASMEM  (2 * BUFB)

__global__ __launch_bounds__(128, 3) void attn_kernel(float* __restrict__ out)
{
    extern __shared__ uint32_t sm[];
    const uint32_t sb = smem_u32(sm);

    const int t    = threadIdx.x;
    const int b    = blockIdx.y;
    const int warp = t >> 5;
    const int lane = t & 31;
    const int q    = lane & 3;
    const int r4   = lane >> 2;

    const int qt     = (NQT - 1) - (int)blockIdx.x;
    const int nkt128 = (qt + 2) >> 1;
    const int row_lo = qt * 64 + warp * 16 + r4;

    const uint32_t kinv = (uint32_t)((8 * ((lane >> 4) & 1) + (lane & 7)) * PW * 4
                                     + 8 * ((lane >> 3) & 1) * 2);
    const uint32_t vinv = (uint32_t)((8 * ((lane >> 3) & 1) + (lane & 7)) * PW * 4
                                     + 8 * ((lane >> 4) & 1) * 2);
    const uint32_t bsum = (r4 == 0) ? 0x3C003C00u : 0u;  // ones col-0 B-frag

    const __half* kb0 = g_k + (size_t)(b * TDIM) * HDIM;
    const __half* vb0 = g_v + (size_t)(b * TDIM) * HDIM;

    auto stage = [&](int kt, int buf) {
        const __half* kb = kb0 + (size_t)kt * 128 * HDIM;
        const __half* vb = vb0 + (size_t)kt * 128 * HDIM;
        const uint32_t kd = sb + (uint32_t)buf * BUFB;
        const uint32_t vd = kd + (uint32_t)T128W * 4;
        #pragma unroll
        for (int i = 0; i < 8; i++) {
            int f = t + i * 128, r = f >> 3, ch = f & 7;
            cpa16(kd + (uint32_t)(r * PW + ch * 4) * 4u, kb + r * HDIM + ch * 8);
            cpa16(vd + (uint32_t)(r * PW + ch * 4) * 4u, vb + r * HDIM + ch * 8);
        }
        CPCOMMIT();
    };

    stage(0, 0);

    uint32_t qa[4][4];
    {
        const __half* qp = g_q + (size_t)(b * TDIM + row_lo) * HDIM;
        #pragma unroll
        for (int kc = 0; kc < 4; kc++) {
            qa[kc][0] = *(const uint32_t*)&qp[16 * kc + 2 * q];
            qa[kc][1] = *(const uint32_t*)&qp[8 * HDIM + 16 * kc + 2 * q];
            qa[kc][2] = *(const uint32_t*)&qp[16 * kc + 2 * q + 8];
            qa[kc][3] = *(const uint32_t*)&qp[8 * HDIM + 16 * kc + 2 * q + 8];
        }
    }

    float4 o[8];
    #pragma unroll
    for (int i = 0; i < 8; i++) o[i] = make_float4(0.f, 0.f, 0.f, 0.f);
    float m0 = -1e30f, m1 = -1e30f, l0 = 0.f, l1 = 0.f;

    for (int kt = 0; kt < nkt128; kt++) {
        if (kt + 1 < nkt128) { stage(kt + 1, (kt + 1) & 1); CPWAIT(1); }
        else                 { CPWAIT(0); }
        __syncthreads();

        const uint32_t kbase = sb + (uint32_t)(kt & 1) * BUFB;

        #pragma unroll 1
        for (int sub = 0; sub < 2; sub++) {
            const int cb = kt * 128 + sub * 64;
            if (cb > qt * 64) break;

            const uint32_t kb = kbase + kinv + (uint32_t)(sub * 64 * PW * 4);
            const uint32_t vb = kbase + (uint32_t)T128W * 4 + vinv
                                + (uint32_t)(sub * 64 * PW * 4);

            // S = Q @ K^T  (scores in base-2 units)
            float4 st[8];
            #pragma unroll
            for (int i = 0; i < 8; i++) st[i] = make_float4(0.f, 0.f, 0.f, 0.f);
            #pragma unroll
            for (int kc = 0; kc < 4; kc++)
                #pragma unroll
                for (int ncp = 0; ncp < 4; ncp++) {
                    uint32_t b0, b1, b2, b3;
                    ldm4(b0, b1, b2, b3,
                         kb + (uint32_t)(ncp * 16 * PW * 4 + kc * 32));
                    mma16(st[2 * ncp],     qa[kc], b0, b1);
                    mma16(st[2 * ncp + 1], qa[kc], b2, b3);
                }

            if (cb == qt * 64) {     // diagonal sub-tile: causal mask
                const int cq = cb + 2 * q;
                #pragma unroll
                for (int nc = 0; nc < 8; nc++) {
                    const int col = cq + 8 * nc;
                    if (col > row_lo)         st[nc].x = -1e30f;
                    if (col + 1 > row_lo)     st[nc].y = -1e30f;
                    if (col > row_lo + 8)     st[nc].z = -1e30f;
                    if (col + 1 > row_lo + 8) st[nc].w = -1e30f;
                }
            }

            // online softmax, base 2
            float mx0 = st[0].x, mx1 = st[0].z;
            #pragma unroll
            for (int nc = 0; nc < 8; nc++) {
                mx0 = fmaxf(mx0, fmaxf(st[nc].x, st[nc].y));
                mx1 = fmaxf(mx1, fmaxf(st[nc].z, st[nc].w));
            }
            mx0 = fmaxf(mx0, __shfl_xor_sync(0xffffffffu, mx0, 1));
            mx0 = fmaxf(mx0, __shfl_xor_sync(0xffffffffu, mx0, 2));
            mx1 = fmaxf(mx1, __shfl_xor_sync(0xffffffffu, mx1, 1));
            mx1 = fmaxf(mx1, __shfl_xor_sync(0xffffffffu, mx1, 2));
            const float mn0 = fmaxf(m0, mx0), mn1 = fmaxf(m1, mx1);
            const float corr0 = ex2f(m0 - mn0), corr1 = ex2f(m1 - mn1);
            m0 = mn0; m1 = mn1;

            if (__ballot_sync(0xffffffffu, (corr0 != 1.f) || (corr1 != 1.f))) {
                #pragma unroll
                for (int nc = 0; nc < 8; nc++) {
                    o[nc].x *= corr0; o[nc].y *= corr0;
                    o[nc].z *= corr1; o[nc].w *= corr1;
                }
            }

            // p = 2^(s-mn) in f16x2 (A-frags directly); row sums via HMMA;
            // O += P @ V fused in the same kc loop.
            float4 sums = make_float4(0.f, 0.f, 0.f, 0.f);
            #pragma unroll
            for (int kc = 0; kc < 4; kc++) {
                uint32_t pa[4];
                pa[0] = ex2h2(packh2(st[2*kc].x   - mn0, st[2*kc].y   - mn0));
                pa[1] = ex2h2(packh2(st[2*kc].z   - mn1, st[2*kc].w   - mn1));
                pa[2] = ex2h2(packh2(st[2*kc+1].x - mn0, st[2*kc+1].y - mn0));
                pa[3] = ex2h2(packh2(st[2*kc+1].z - mn1, st[2*kc+1].w - mn1));
                mma16(sums, pa, bsum, bsum);
                #pragma unroll
                for (int ncp = 0; ncp < 4; ncp++) {
                    uint32_t b0, b1, b2, b3;
                    ldm4t(b0, b1, b2, b3,
                          vb + (uint32_t)(kc * 16 * PW * 4 + ncp * 32));
                    mma16(o[2 * ncp],     pa, b0, b1);
                    mma16(o[2 * ncp + 1], pa, b2, b3);
                }
            }
            const float s0 = __shfl_sync(0xffffffffu, sums.x, lane & ~3);
            const float s1 = __shfl_sync(0xffffffffu, sums.z, lane & ~3);
            l0 = l0 * corr0 + s0;
            l1 = l1 * corr1 + s1;
        }
        __syncthreads();
    }

    // epilogue
    const float inv0 = 1.0f / l0, inv1 = 1.0f / l1;
    float* ob = out + (size_t)(b * TDIM + row_lo) * HDIM;
    #pragma unroll
    for (int nc = 0; nc < 8; nc++) {
        const int col = 8 * nc + 2 * q;
        *(float2*)&ob[col]            = make_float2(o[nc].x * inv0, o[nc].y * inv0);
        *(float2*)&ob[8 * HDIM + col] = make_float2(o[nc].z * inv1, o[nc].w * inv1);
    }
}

// ---------------------------------------------------------------------------
extern "C" void kernel_launch(void* const* d_in, const int* in_sizes, int n_in,
                              void* d_out, int out_size)
{
    const float* x  = (const float*)d_in[0];
    const float* Wk = (const float*)d_in[1];
    const float* Wq = (const float*)d_in[2];
    const float* Wv = (const float*)d_in[3];
    float* out = (float*)d_out;

    proj_kernel<<<BT / 128, 512>>>(x, Wk, Wq, Wv);

    cudaFuncSetAttribute(attn_kernel,
                         cudaFuncAttributeMaxDynamicSharedMemorySize, ASMEM);
    dim3 agrid(NQT, BATCH);
    attn_kernel<<<agrid, 128, ASMEM>>>(out);
}

// round 17
// speedup vs baseline: 1.1811x; 1.0236x over previous
#include <cuda_runtime.h>
#include <cuda_fp16.h>
#include <cstdint>

#define BATCH 32
#define TDIM  2048
#define CDIM  384
#define HDIM  64
#define BT    (BATCH * TDIM)
#define NQT   32

// Projected activations in f16. q pre-scaled by 0.125*log2(e) (base-2 softmax).
__device__ __align__(256) __half g_q[BT * HDIM];
__device__ __align__(256) __half g_k[BT * HDIM];
__device__ __align__(256) __half g_v[BT * HDIM];

#define QSCALE 0.1803368801111f   // 0.125 * log2(e)

__device__ __forceinline__ uint32_t packh2(float lo, float hi) {
    uint32_t r;
    asm("cvt.rn.f16x2.f32 %0, %1, %2;" : "=r"(r) : "f"(hi), "f"(lo));
    return r;
}
__device__ __forceinline__ float ex2f(float x) {
    float r; asm("ex2.approx.f32 %0, %1;" : "=f"(r) : "f"(x)); return r;
}
__device__ __forceinline__ uint32_t ex2h2(uint32_t x) {
    uint32_t r; asm("ex2.approx.f16x2 %0, %1;" : "=r"(r) : "r"(x)); return r;
}
__device__ __forceinline__ uint32_t smem_u32(const void* p) {
    uint32_t a;
    asm("{ .reg .u64 t; cvta.to.shared.u64 t, %1; cvt.u32.u64 %0, t; }"
        : "=r"(a) : "l"(p));
    return a;
}
__device__ __forceinline__ void cpa16(uint32_t dst, const void* src) {
    asm volatile("cp.async.cg.shared.global [%0], [%1], 16;"
                 :: "r"(dst), "l"(src));
}
#define CPCOMMIT() asm volatile("cp.async.commit_group;" ::: "memory")
#define CPWAIT(n)  asm volatile("cp.async.wait_group %0;" :: "n"(n) : "memory")

__device__ __forceinline__ void ldm4(uint32_t& r0, uint32_t& r1,
                                     uint32_t& r2, uint32_t& r3, uint32_t a) {
    asm volatile("ldmatrix.sync.aligned.m8n8.x4.shared.b16 {%0,%1,%2,%3}, [%4];"
                 : "=r"(r0), "=r"(r1), "=r"(r2), "=r"(r3) : "r"(a));
}
__device__ __forceinline__ void ldm4t(uint32_t& r0, uint32_t& r1,
                                      uint32_t& r2, uint32_t& r3, uint32_t a) {
    asm volatile("ldmatrix.sync.aligned.m8n8.x4.trans.shared.b16 {%0,%1,%2,%3}, [%4];"
                 : "=r"(r0), "=r"(r1), "=r"(r2), "=r"(r3) : "r"(a));
}

// f16 m16n8k16, fp32 accum.
__device__ __forceinline__ void mma16(float4& c, const uint32_t a[4],
                                      uint32_t b0, uint32_t b1) {
    asm volatile(
        "mma.sync.aligned.m16n8k16.row.col.f32.f16.f16.f32 "
        "{%0,%1,%2,%3}, {%4,%5,%6,%7}, {%8,%9}, {%0,%1,%2,%3};"
        : "+f"(c.x), "+f"(c.y), "+f"(c.z), "+f"(c.w)
        : "r"(a[0]), "r"(a[1]), "r"(a[2]), "r"(a[3]), "r"(b0), "r"(b1));
}

// ---------------------------------------------------------------------------
// Projection: [K|Q|V] = x @ [Wk|Wq|Wv], f16 m16n8k16 + ldmatrix.
// Block = 512 thr (16 warps), 128 rows x 192 cols, ONE x read.
// Double-buffered smem, ONE barrier per chunk: STS(c) -> sync ->
// prefetch LDG(c+1) -> compute(c). Warp grid 8 rowg x 2 colg, c[12].
// ---------------------------------------------------------------------------
#define XPW 20     // Xs pitch in words (32 f16 + pad)
#define WPW 100    // Ws pitch in words (192 f16 + pad)

__global__ __launch_bounds__(512, 1) void proj_kernel(
    const float* __restrict__ x,
    const float* __restrict__ Wk,
    const float* __restrict__ Wq,
    const float* __restrict__ Wv)
{
    __shared__ uint32_t Xs[2][128 * XPW];
    __shared__ uint32_t Ws[2][32 * WPW];

    const int t    = threadIdx.x;
    const int wid  = t >> 5;
    const int lane = t & 31;
    const int q    = lane & 3;
    const int r4   = lane >> 2;
    const int rowg = wid & 7;      // 8 row-groups of 16 rows
    const int colg = wid >> 3;     // 2 col-groups of 96 cols
    const int row0 = blockIdx.x * 128;
    const float* Wm[3] = {Wk, Wq, Wv};

    const uint32_t ainv = (uint32_t)((rowg * 16 + 8 * ((lane >> 3) & 1) + (lane & 7))
                                     * (XPW * 4) + ((lane >> 4) & 1) * 16);
    const uint32_t winv = (uint32_t)((8 * ((lane >> 3) & 1) + (lane & 7)) * (WPW * 4)
                                     + 8 * ((lane >> 4) & 1) * 2 + colg * 192);

    float4 c[12];
    #pragma unroll
    for (int i = 0; i < 12; i++) c[i] = make_float4(0.f, 0.f, 0.f, 0.f);

    // staging maps: x — thread t -> row t>>2, col-8-group t&3 (16 f32)
    //               W — unit u: row u/24, c8 u%24 (8 f32); u = t and t+512 (t<256)
    const int xrow = t >> 2, xc8 = t & 3;
    const int w0row = t / 24,         w0c8 = t % 24;
    const int w1row = (t + 512) / 24, w1c8 = (t + 512) % 24;

    float4 xr[2], wr0[2], wr1[2];
    auto loadc = [&](int cc) {
        const int c0 = cc * 32;
        const float* xp = &x[(row0 + xrow) * CDIM + c0 + xc8 * 8];
        xr[0] = *(const float4*)xp;
        xr[1] = *(const float4*)(xp + 4);
        const float* wp0 = &Wm[w0c8 >> 3][(c0 + w0row) * HDIM + (w0c8 & 7) * 8];
        wr0[0] = *(const float4*)wp0;
        wr0[1] = *(const float4*)(wp0 + 4);
        if (t < 256) {
            const float* wp1 = &Wm[w1c8 >> 3][(c0 + w1row) * HDIM + (w1c8 & 7) * 8];
            wr1[0] = *(const float4*)wp1;
            wr1[1] = *(const float4*)(wp1 + 4);
        }
    };

    loadc(0);

    for (int cc = 0; cc < 12; cc++) {
        const int ph = cc & 1;
        {   // STS chunk cc into buffer ph (safe: all warps finished compute
            // on this buffer before passing the PREVIOUS iteration's barrier)
            uint4 p;
            p.x = packh2(xr[0].x, xr[0].y); p.y = packh2(xr[0].z, xr[0].w);
            p.z = packh2(xr[1].x, xr[1].y); p.w = packh2(xr[1].z, xr[1].w);
            *(uint4*)&Xs[ph][xrow * XPW + xc8 * 4] = p;

            p.x = packh2(wr0[0].x, wr0[0].y); p.y = packh2(wr0[0].z, wr0[0].w);
            p.z = packh2(wr0[1].x, wr0[1].y); p.w = packh2(wr0[1].z, wr0[1].w);
            *(uint4*)&Ws[ph][w0row * WPW + w0c8 * 4] = p;
            if (t < 256) {
                p.x = packh2(wr1[0].x, wr1[0].y); p.y = packh2(wr1[0].z, wr1[0].w);
                p.z = packh2(wr1[1].x, wr1[1].y); p.w = packh2(wr1[1].z, wr1[1].w);
                *(uint4*)&Ws[ph][w1row * WPW + w1c8 * 4] = p;
            }
        }
        __syncthreads();     // single barrier per chunk

        if (cc + 1 < 12) loadc(cc + 1);

        const uint32_t xsb = smem_u32(Xs[ph]), wsb = smem_u32(Ws[ph]);
        uint32_t a[2][4];
        ldm4(a[0][0], a[0][1], a[0][2], a[0][3], xsb + ainv);
        ldm4(a[1][0], a[1][1], a[1][2], a[1][3], xsb + ainv + 32);
        #pragma unroll
        for (int p5 = 0; p5 < 6; p5++)
            #pragma unroll
            for (int kc = 0; kc < 2; kc++) {
                uint32_t b0, b1, b2, b3;
                ldm4t(b0, b1, b2, b3,
                      wsb + winv + (uint32_t)(kc * 16 * WPW * 4 + p5 * 32));
                mma16(c[2 * p5],     a[kc], b0, b1);
                mma16(c[2 * p5 + 1], a[kc], b2, b3);
            }
    }

    const int row = row0 + rowg * 16 + r4;
    __half* outp[3] = {g_k, g_q, g_v};
    #pragma unroll
    for (int idx = 0; idx < 12; idx++) {
        const int gcol = colg * 96 + idx * 8 + 2 * q;
        const int mat  = gcol >> 6, col = gcol & 63;
        const float sc = (mat == 1) ? QSCALE : 1.0f;   // Q pre-scaled (base-2)
        float4 v = c[idx];
        *(uint32_t*)&outp[mat][row * HDIM + col]       = packh2(v.x * sc, v.y * sc);
        *(uint32_t*)&outp[mat][(row + 8) * HDIM + col] = packh2(v.z * sc, v.w * sc);
    }
}

// ---------------------------------------------------------------------------
// Flash attention: R11 compute structure, 64-key double-buffered STATIC smem
// (36.9 KB) + __launch_bounds__(128,4) -> 4 CTAs/SM, 16 warps/SM.
// Block = 128 thr, 64 q-rows, grid (32, 32) heavy-first.
// ---------------------------------------------------------------------------
#define PW    36
#define TILEW (64 * PW)

__global__ __launch_bounds__(128, 4) void attn_kernel(float* __restrict__ out)
{
    __shared__ uint32_t Kbuf[2][TILEW];
    __shared__ uint32_t Vbuf[2][TILEW];

    const int t    = threadIdx.x;
    const int b    = blockIdx.y;
    const int warp = t >> 5;
    const int lane = t & 31;
    const int q    = lane & 3;
    const int r4   = lane >> 2;

    const int qt     = (NQT - 1) - (int)blockIdx.x;   // heavy first
    const int nkt    = qt + 1;
    const int row_lo = qt * 64 + warp * 16 + r4;

    const uint32_t kinv = (uint32_t)((8 * ((lane >> 4) & 1) + (lane & 7)) * PW * 4
                                     + 8 * ((lane >> 3) & 1) * 2);
    const uint32_t vinv = (uint32_t)((8 * ((lane >> 3) & 1) + (lane & 7)) * PW * 4
                                     + 8 * ((lane >> 4) & 1) * 2);
    const uint32_t bsum = (r4 == 0) ? 0x3C003C00u : 0u;  // ones col-0 B-frag
    const uint32_t kbs[2] = { smem_u32(Kbuf[0]), smem_u32(Kbuf[1]) };
    const uint32_t vbs[2] = { smem_u32(Vbuf[0]), smem_u32(Vbuf[1]) };

    const __half* kb0 = g_k + (size_t)(b * TDIM) * HDIM;
    const __half* vb0 = g_v + (size_t)(b * TDIM) * HDIM;

    auto stage = [&](int kt, int buf) {
        const __half* kb = kb0 + (size_t)kt * 64 * HDIM;
        const __half* vb = vb0 + (size_t)kt * 64 * HDIM;
        #pragma unroll
        for (int i = 0; i < 4; i++) {
            int f = t + i * 128, r = f >> 3, ch = f & 7;
            cpa16(kbs[buf] + (uint32_t)(r * PW + ch * 4) * 4u, kb + r * HDIM + ch * 8);
            cpa16(vbs[buf] + (uint32_t)(r * PW + ch * 4) * 4u, vb + r * HDIM + ch * 8);
        }
        CPCOMMIT();
    };

    stage(0, 0);

    uint32_t qa[4][4];
    {
        const __half* qp = g_q + (size_t)(b * TDIM + row_lo) * HDIM;
        #pragma unroll
        for (int kc = 0; kc < 4; kc++) {
            qa[kc][0] = *(const uint32_t*)&qp[16 * kc + 2 * q];
            qa[kc][1] = *(const uint32_t*)&qp[8 * HDIM + 16 * kc + 2 * q];
            qa[kc][2] = *(const uint32_t*)&qp[16 * kc + 2 * q + 8];
            qa[kc][3] = *(const uint32_t*)&qp[8 * HDIM + 16 * kc + 2 * q + 8];
        }
    }

    float4 o[8];
    #pragma unroll
    for (int i = 0; i < 8; i++) o[i] = make_float4(0.f, 0.f, 0.f, 0.f);
    float m0 = -1e30f, m1 = -1e30f, l0 = 0.f, l1 = 0.f;

    for (int kt = 0; kt < nkt; kt++) {
        if (kt + 1 < nkt) { stage(kt + 1, (kt + 1) & 1); CPWAIT(1); }
        else              { CPWAIT(0); }
        __syncthreads();

        const uint32_t kb = kbs[kt & 1] + kinv;
        const uint32_t vb = vbs[kt & 1] + vinv;

        // S = Q @ K^T  (scores in base-2 units)
        float4 st[8];
        #pragma unroll
        for (int i = 0; i < 8; i++) st[i] = make_float4(0.f, 0.f, 0.f, 0.f);
        #pragma unroll
        for (int kc = 0; kc < 4; kc++)
            #pragma unroll
            for (int ncp = 0; ncp < 4; ncp++) {
                uint32_t b0, b1, b2, b3;
                ldm4(b0, b1, b2, b3,
                     kb + (uint32_t)(ncp * 16 * PW * 4 + kc * 32));
                mma16(st[2 * ncp],     qa[kc], b0, b1);
                mma16(st[2 * ncp + 1], qa[kc], b2, b3);
            }

        if (kt == nkt - 1) {     // diagonal tile: causal mask
            const int cq = kt * 64 + 2 * q;
            #pragma unroll
            for (int nc = 0; nc < 8; nc++) {
                const int col = cq + 8 * nc;
                if (col > row_lo)         st[nc].x = -1e30f;
                if (col + 1 > row_lo)     st[nc].y = -1e30f;
                if (col > row_lo + 8)     st[nc].z = -1e30f;
                if (col + 1 > row_lo + 8) st[nc].w = -1e30f;
            }
        }

        // online softmax, base 2
        float mx0 = st[0].x, mx1 = st[0].z;
        #pragma unroll
        for (int nc = 0; nc < 8; nc++) {
            mx0 = fmaxf(mx0, fmaxf(st[nc].x, st[nc].y));
            mx1 = fmaxf(mx1, fmaxf(st[nc].z, st[nc].w));
        }
        mx0 = fmaxf(mx0, __shfl_xor_sync(0xffffffffu, mx0, 1));
        mx0 = fmaxf(mx0, __shfl_xor_sync(0xffffffffu, mx0, 2));
        mx1 = fmaxf(mx1, __shfl_xor_sync(0xffffffffu, mx1, 1));
        mx1 = fmaxf(mx1, __shfl_xor_sync(0xffffffffu, mx1, 2));
        const float mn0 = fmaxf(m0, mx0), mn1 = fmaxf(m1, mx1);
        const float corr0 = ex2f(m0 - mn0), corr1 = ex2f(m1 - mn1);
        m0 = mn0; m1 = mn1;

        if (__ballot_sync(0xffffffffu, (corr0 != 1.f) || (corr1 != 1.f))) {
            #pragma unroll
            for (int nc = 0; nc < 8; nc++) {
                o[nc].x *= corr0; o[nc].y *= corr0;
                o[nc].z *= corr1; o[nc].w *= corr1;
            }
        }

        // p = 2^(s-mn) in f16x2 (A-frags directly); row sums via HMMA;
        // O += P @ V fused in the same kc loop.
        float4 sums = make_float4(0.f, 0.f, 0.f, 0.f);
        #pragma unroll
        for (int kc = 0; kc < 4; kc++) {
            uint32_t pa[4];
            pa[0] = ex2h2(packh2(st[2*kc].x   - mn0, st[2*kc].y   - mn0));
            pa[1] = ex2h2(packh2(st[2*kc].z   - mn1, st[2*kc].w   - mn1));
            pa[2] = ex2h2(packh2(st[2*kc+1].x - mn0, st[2*kc+1].y - mn0));
            pa[3] = ex2h2(packh2(st[2*kc+1].z - mn1, st[2*kc+1].w - mn1));
            mma16(sums, pa, bsum, bsum);
            #pragma unroll
            for (int ncp = 0; ncp < 4; ncp++) {
                uint32_t b0, b1, b2, b3;
                ldm4t(b0, b1, b2, b3,
                      vb + (uint32_t)(kc * 16 * PW * 4 + ncp * 32));
                mma16(o[2 * ncp],     pa, b0, b1);
                mma16(o[2 * ncp + 1], pa, b2, b3);
            }
        }
        const float s0 = __shfl_sync(0xffffffffu, sums.x, lane & ~3);
        const float s1 = __shfl_sync(0xffffffffu, sums.z, lane & ~3);
        l0 = l0 * corr0 + s0;
        l1 = l1 * corr1 + s1;

        __syncthreads();   // reads done before next iteration's cp.async
    }

    // epilogue
    const float inv0 = 1.0f / l0, inv1 = 1.0f / l1;
    float* ob = out + (size_t)(b * TDIM + row_lo) * HDIM;
    #pragma unroll
    for (int nc = 0; nc < 8; nc++) {
        const int col = 8 * nc + 2 * q;
        *(float2*)&ob[col]            = make_float2(o[nc].x * inv0, o[nc].y * inv0);
        *(float2*)&ob[8 * HDIM + col] = make_float2(o[nc].z * inv1, o[nc].w * inv1);
    }
}

// ---------------------------------------------------------------------------
extern "C" void kernel_launch(void* const* d_in, const int* in_sizes, int n_in,
                              void* d_out, int out_size)
{
    const float* x  = (const float*)d_in[0];
    const float* Wk = (const float*)d_in[1];
    const float* Wq = (const float*)d_in[2];
    const float* Wv = (const float*)d_in[3];
    float* out = (float*)d_out;

    proj_kernel<<<BT / 128, 512>>>(x, Wk, Wq, Wv);

    dim3 agrid(NQT, BATCH);
    attn_kernel<<<agrid, 128>>>(out);
}